// round 5
// baseline (speedup 1.0000x reference)
#include <cuda_runtime.h>

#define HVAL 256
#define HINGE 100.0f

__device__ __forceinline__ float safe_sqrt(float x) {
    return x > 0.0f ? sqrtf(x) : 0.0f;
}

__global__ __launch_bounds__(256, 6)
void traj_cost_kernel(const float* __restrict__ pos,   // [B,H,3]
                      const float* __restrict__ rot,   // [B,H,3,3]
                      const float* __restrict__ gpos,  // [H,3]
                      const float* __restrict__ grot,  // [H,3,3]
                      float* __restrict__ out,         // [3,B*H]
                      int B)
{
    __shared__ float s_rot [HVAL * 9];  // 9.2 KB
    __shared__ float s_pos [HVAL * 3];  // 3.1 KB
    __shared__ float s_grot[HVAL * 9];  // 9.2 KB
    __shared__ float s_gpos[HVAL * 3];  // 3.1 KB  (total 24.6 KB)

    const int b   = blockIdx.x;
    const int tid = threadIdx.x;

    // --- Coalesced float4 staging (rot/pos from DRAM, goal arrays from L2) ---
    {
        const float4* rsrc = reinterpret_cast<const float4*>(rot + (size_t)b * (HVAL * 9));
        float4*       rdst = reinterpret_cast<float4*>(s_rot);
        const float4* gsrc = reinterpret_cast<const float4*>(grot);
        float4*       gdst = reinterpret_cast<float4*>(s_grot);
        // 2304 floats = 576 float4 each
        rdst[tid]       = rsrc[tid];
        rdst[tid + 256] = rsrc[tid + 256];
        gdst[tid]       = gsrc[tid];
        gdst[tid + 256] = gsrc[tid + 256];
        if (tid < 64) {
            rdst[tid + 512] = rsrc[tid + 512];
            gdst[tid + 512] = gsrc[tid + 512];
        }

        const float4* psrc = reinterpret_cast<const float4*>(pos + (size_t)b * (HVAL * 3));
        float4*       pdst = reinterpret_cast<float4*>(s_pos);
        const float4* qsrc = reinterpret_cast<const float4*>(gpos);
        float4*       qdst = reinterpret_cast<float4*>(s_gpos);
        // 768 floats = 192 float4 each
        if (tid < 192) {
            pdst[tid] = psrc[tid];
            qdst[tid] = qsrc[tid];
        }
    }
    __syncthreads();

    const int h = tid;

    // Conflict-free shared reads (strides 9 and 3 are coprime with 32 banks)
    float R[9], p[3], G[9], pg[3];
    #pragma unroll
    for (int i = 0; i < 9; i++) R[i] = s_rot[h * 9 + i];
    #pragma unroll
    for (int i = 0; i < 9; i++) G[i] = s_grot[h * 9 + i];
    #pragma unroll
    for (int i = 0; i < 3; i++) p[i] = s_pos[h * 3 + i];
    #pragma unroll
    for (int i = 0; i < 3; i++) pg[i] = s_gpos[h * 3 + i];

    // ee_t_g[i] = (R^T p)[i] - (G^T pg)[i]
    float t[3];
    #pragma unroll
    for (int i = 0; i < 3; i++) {
        float eto = fmaf(R[i], p[0], fmaf(R[3 + i], p[1], R[6 + i] * p[2]));
        float otg = fmaf(G[i], pg[0], fmaf(G[3 + i], pg[1], G[6 + i] * pg[2]));
        t[i] = eto - otg;
    }
    float pos_err   = fmaf(t[0], t[0], fmaf(t[1], t[1], t[2] * t[2]));
    float goal_dist = safe_sqrt(pos_err);

    // ee_R_g[i][j] = sum_k G[k][i]*R[k][j] ; d = I - ee_R_g ; rn[i] = ||d[i,:]||
    float rn[3];
    #pragma unroll
    for (int i = 0; i < 3; i++) {
        float rsq = 0.0f;
        #pragma unroll
        for (int j = 0; j < 3; j++) {
            float m = fmaf(G[i], R[j], fmaf(G[3 + i], R[3 + j], G[6 + i] * R[6 + j]));
            float d = (i == j ? 1.0f : 0.0f) - m;
            rsq = fmaf(d, d, rsq);
        }
        rn[i] = safe_sqrt(rsq);
    }

    float rn_sum       = rn[0] + rn[1] + rn[2];
    float rot_err_norm = safe_sqrt(fmaf(rn[0], rn[0], fmaf(rn[1], rn[1], rn[2] * rn[2])));
    float rot_err      = rn_sum * rn_sum;
    if (goal_dist > HINGE) rot_err = 0.0f;

    float cost = safe_sqrt(rot_err) + safe_sqrt(pos_err);

    const size_t BH = (size_t)B * HVAL;
    const size_t n  = (size_t)b * HVAL + h;
    out[n]          = cost;
    out[BH + n]     = rot_err_norm;
    out[2 * BH + n] = goal_dist;
}

extern "C" void kernel_launch(void* const* d_in, const int* in_sizes, int n_in,
                              void* d_out, int out_size) {
    // Bind inputs BY SIZE (robust to harness ordering):
    //   H*3 -> gpos, H*9 -> grot, B*H*3 -> pos, B*H*9 -> rot
    int idx[4] = {0, 1, 2, 3};
    for (int i = 1; i < 4; i++) {
        int v = idx[i];
        int j = i - 1;
        while (j >= 0 && in_sizes[idx[j]] > in_sizes[v]) { idx[j + 1] = idx[j]; j--; }
        idx[j + 1] = v;
    }
    const float* gpos = (const float*)d_in[idx[0]];
    const float* grot = (const float*)d_in[idx[1]];
    const float* pos  = (const float*)d_in[idx[2]];
    const float* rot  = (const float*)d_in[idx[3]];

    const int H = in_sizes[idx[0]] / 3;          // 256
    const int B = in_sizes[idx[3]] / (9 * H);    // 8192

    float* out = (float*)d_out;
    traj_cost_kernel<<<B, 256>>>(pos, rot, gpos, grot, out, B);
}

// round 6
// speedup vs baseline: 1.1511x; 1.1511x over previous
#include <cuda_runtime.h>
#include <cstdint>

#define HVAL 256
#define HINGE 100.0f
#define NCTA 888          // 148 SMs * 6 CTAs: one resident wave

__device__ __forceinline__ float safe_sqrt(float x) {
    return x > 0.0f ? sqrtf(x) : 0.0f;
}

__device__ __forceinline__ void cp_async16(uint32_t smem_dst, const void* gmem_src) {
    asm volatile("cp.async.cg.shared.global [%0], [%1], 16;\n"
                 :: "r"(smem_dst), "l"(gmem_src));
}
__device__ __forceinline__ void cp_commit() {
    asm volatile("cp.async.commit_group;\n");
}
template<int N>
__device__ __forceinline__ void cp_wait() {
    asm volatile("cp.async.wait_group %0;\n" :: "n"(N));
}

__global__ __launch_bounds__(256, 6)
void traj_cost_kernel(const float* __restrict__ pos,   // [B,H,3]
                      const float* __restrict__ rot,   // [B,H,3,3]
                      const float* __restrict__ gpos,  // [H,3]
                      const float* __restrict__ grot,  // [H,3,3]
                      float* __restrict__ out,         // [3,B*H]
                      int B)
{
    // Double-buffered tiles: (2304 + 768) * 4 B = 12.3 KB per buffer, 24.6 KB total
    __shared__ float s_rot[2][HVAL * 9];
    __shared__ float s_pos[2][HVAL * 3];

    const int tid = threadIdx.x;
    const int h   = tid;

    // ---- Goal data: load ONCE per CTA into registers ----
    float G[9], otg[3];
    #pragma unroll
    for (int i = 0; i < 9; i++) G[i] = __ldg(&grot[h * 9 + i]);
    {
        float pg0 = __ldg(&gpos[h * 3 + 0]);
        float pg1 = __ldg(&gpos[h * 3 + 1]);
        float pg2 = __ldg(&gpos[h * 3 + 2]);
        #pragma unroll
        for (int i = 0; i < 3; i++)
            otg[i] = fmaf(G[i], pg0, fmaf(G[3 + i], pg1, G[6 + i] * pg2));
    }

    // smem byte addresses for cp.async
    uint32_t srot[2], spos[2];
    srot[0] = (uint32_t)__cvta_generic_to_shared(s_rot[0]);
    srot[1] = (uint32_t)__cvta_generic_to_shared(s_rot[1]);
    spos[0] = (uint32_t)__cvta_generic_to_shared(s_pos[0]);
    spos[1] = (uint32_t)__cvta_generic_to_shared(s_pos[1]);

    // Stage one tile (576 rot float4 + 192 pos float4) via cp.async
    auto stage = [&](int buf, int b) {
        const float4* rsrc = reinterpret_cast<const float4*>(rot + (size_t)b * (HVAL * 9));
        cp_async16(srot[buf] + (uint32_t)(tid      ) * 16, rsrc + tid);
        cp_async16(srot[buf] + (uint32_t)(tid + 256) * 16, rsrc + tid + 256);
        if (tid < 64)
            cp_async16(srot[buf] + (uint32_t)(tid + 512) * 16, rsrc + tid + 512);
        if (tid < 192) {
            const float4* psrc = reinterpret_cast<const float4*>(pos + (size_t)b * (HVAL * 3));
            cp_async16(spos[buf] + (uint32_t)tid * 16, psrc + tid);
        }
    };

    const size_t BH = (size_t)B * HVAL;

    int b   = blockIdx.x;     // grid = NCTA <= B always here
    int buf = 0;

    stage(0, b);
    cp_commit();

    for (; b < B; b += NCTA) {
        const int nb = b + NCTA;
        if (nb < B) {
            stage(buf ^ 1, nb);
            cp_commit();
            cp_wait<1>();      // current tile complete
        } else {
            cp_wait<0>();
        }
        __syncthreads();       // tile visible to all threads

        // ---- Compute on current tile ----
        float R[9], p[3];
        #pragma unroll
        for (int i = 0; i < 9; i++) R[i] = s_rot[buf][h * 9 + i];
        #pragma unroll
        for (int i = 0; i < 3; i++) p[i] = s_pos[buf][h * 3 + i];

        // ee_t_g[i] = (R^T p)[i] - otg[i]
        float t0 = fmaf(R[0], p[0], fmaf(R[3], p[1], R[6] * p[2])) - otg[0];
        float t1 = fmaf(R[1], p[0], fmaf(R[4], p[1], R[7] * p[2])) - otg[1];
        float t2 = fmaf(R[2], p[0], fmaf(R[5], p[1], R[8] * p[2])) - otg[2];
        float pos_err   = fmaf(t0, t0, fmaf(t1, t1, t2 * t2));
        float goal_dist = safe_sqrt(pos_err);

        // ee_R_g[i][j] = sum_k G[k][i]*R[k][j]; d = I - ee_R_g; rn[i] = ||d[i,:]||
        float rn[3];
        #pragma unroll
        for (int i = 0; i < 3; i++) {
            float rsq = 0.0f;
            #pragma unroll
            for (int j = 0; j < 3; j++) {
                float m = fmaf(G[i], R[j], fmaf(G[3 + i], R[3 + j], G[6 + i] * R[6 + j]));
                float d = (i == j ? 1.0f : 0.0f) - m;
                rsq = fmaf(d, d, rsq);
            }
            rn[i] = safe_sqrt(rsq);
        }

        float rn_sum       = rn[0] + rn[1] + rn[2];
        float rot_err_norm = safe_sqrt(fmaf(rn[0], rn[0], fmaf(rn[1], rn[1], rn[2] * rn[2])));
        // sqrt(rot_err) with hinge; rn_sum >= 0 so sqrt(rn_sum^2) = rn_sum
        float sq_rot = (goal_dist <= HINGE) ? rn_sum : 0.0f;

        float cost = sq_rot + goal_dist;   // WEIGHT = (1,1); sqrt(pos_err) = goal_dist

        const size_t n = (size_t)b * HVAL + h;
        out[n]          = cost;
        out[BH + n]     = rot_err_norm;
        out[2 * BH + n] = goal_dist;

        __syncthreads();       // all done with buf before it is overwritten next round
        buf ^= 1;
    }
}

extern "C" void kernel_launch(void* const* d_in, const int* in_sizes, int n_in,
                              void* d_out, int out_size) {
    // Bind inputs BY SIZE (robust to harness ordering):
    //   H*3 -> gpos, H*9 -> grot, B*H*3 -> pos, B*H*9 -> rot
    int idx[4] = {0, 1, 2, 3};
    for (int i = 1; i < 4; i++) {
        int v = idx[i];
        int j = i - 1;
        while (j >= 0 && in_sizes[idx[j]] > in_sizes[v]) { idx[j + 1] = idx[j]; j--; }
        idx[j + 1] = v;
    }
    const float* gpos = (const float*)d_in[idx[0]];
    const float* grot = (const float*)d_in[idx[1]];
    const float* pos  = (const float*)d_in[idx[2]];
    const float* rot  = (const float*)d_in[idx[3]];

    const int H = in_sizes[idx[0]] / 3;          // 256
    const int B = in_sizes[idx[3]] / (9 * H);    // 8192

    float* out = (float*)d_out;
    traj_cost_kernel<<<NCTA, 256>>>(pos, rot, gpos, grot, out, B);
}

// round 7
// speedup vs baseline: 1.2249x; 1.0641x over previous
#include <cuda_runtime.h>
#include <cstdint>

#define HVAL 256
#define HINGE 100.0f
#define NCTA 888          // 148 SMs * 6 CTAs: one resident wave

// Approximate sqrt: x * rsqrt(x). rel err ~1e-7, tolerance is 1e-3.
__device__ __forceinline__ float asqrt(float x) {
    return x > 0.0f ? x * rsqrtf(x) : 0.0f;
}

__device__ __forceinline__ void cp_async16(uint32_t smem_dst, const void* gmem_src) {
    asm volatile("cp.async.cg.shared.global [%0], [%1], 16;\n"
                 :: "r"(smem_dst), "l"(gmem_src));
}
__device__ __forceinline__ void cp_commit() {
    asm volatile("cp.async.commit_group;\n");
}
template<int N>
__device__ __forceinline__ void cp_wait() {
    asm volatile("cp.async.wait_group %0;\n" :: "n"(N));
}

__global__ __launch_bounds__(256, 6)
void traj_cost_kernel(const float* __restrict__ pos,   // [B,H,3]
                      const float* __restrict__ rot,   // [B,H,3,3]
                      const float* __restrict__ gpos,  // [H,3]
                      const float* __restrict__ grot,  // [H,3,3]
                      float* __restrict__ out,         // [3,B*H]
                      int B)
{
    // Double-buffered tiles: (2304 + 768) * 4 B = 12.3 KB per buffer
    __shared__ float s_rot[2][HVAL * 9];
    __shared__ float s_pos[2][HVAL * 3];

    const int tid = threadIdx.x;
    const int h   = tid;

    // ---- Goal data: load ONCE into registers; precompute negated otg ----
    float G[9], notg[3];
    #pragma unroll
    for (int i = 0; i < 9; i++) G[i] = __ldg(&grot[h * 9 + i]);
    {
        float pg0 = __ldg(&gpos[h * 3 + 0]);
        float pg1 = __ldg(&gpos[h * 3 + 1]);
        float pg2 = __ldg(&gpos[h * 3 + 2]);
        #pragma unroll
        for (int i = 0; i < 3; i++)
            notg[i] = -fmaf(G[i], pg0, fmaf(G[3 + i], pg1, G[6 + i] * pg2));
    }

    uint32_t srot[2], spos[2];
    srot[0] = (uint32_t)__cvta_generic_to_shared(s_rot[0]);
    srot[1] = (uint32_t)__cvta_generic_to_shared(s_rot[1]);
    spos[0] = (uint32_t)__cvta_generic_to_shared(s_pos[0]);
    spos[1] = (uint32_t)__cvta_generic_to_shared(s_pos[1]);

    // 32-bit incremental offsets (max index B*H*9 = 18.9M < 2^31)
    int roff = blockIdx.x * (HVAL * 9);             // float index into rot
    int poff = blockIdx.x * (HVAL * 3);             // float index into pos
    int n    = blockIdx.x * HVAL + h;               // element index
    const int rstep = NCTA * (HVAL * 9);
    const int pstep = NCTA * (HVAL * 3);
    const int nstep = NCTA * HVAL;
    const int BH    = B * HVAL;

    float* __restrict__ out0 = out;
    float* __restrict__ out1 = out + BH;
    float* __restrict__ out2 = out + 2 * BH;

    auto stage = [&](int buf, int ro, int po) {
        const float4* rsrc = reinterpret_cast<const float4*>(rot + ro);
        cp_async16(srot[buf] + (uint32_t)(tid      ) * 16, rsrc + tid);
        cp_async16(srot[buf] + (uint32_t)(tid + 256) * 16, rsrc + tid + 256);
        if (tid < 64)
            cp_async16(srot[buf] + (uint32_t)(tid + 512) * 16, rsrc + tid + 512);
        if (tid < 192) {
            const float4* psrc = reinterpret_cast<const float4*>(pos + po);
            cp_async16(spos[buf] + (uint32_t)tid * 16, psrc + tid);
        }
    };

    int b   = blockIdx.x;
    int buf = 0;

    stage(0, roff, poff);
    cp_commit();

    for (; b < B; b += NCTA) {
        if (b + NCTA < B) {
            stage(buf ^ 1, roff + rstep, poff + pstep);
            cp_commit();
            cp_wait<1>();
        } else {
            cp_wait<0>();
        }
        __syncthreads();

        float R[9], p[3];
        #pragma unroll
        for (int i = 0; i < 9; i++) R[i] = s_rot[buf][h * 9 + i];
        #pragma unroll
        for (int i = 0; i < 3; i++) p[i] = s_pos[buf][h * 3 + i];

        // t[i] = (R^T p)[i] - otg[i]  (otg folded into FMA chain)
        float t0 = fmaf(R[0], p[0], fmaf(R[3], p[1], fmaf(R[6], p[2], notg[0])));
        float t1 = fmaf(R[1], p[0], fmaf(R[4], p[1], fmaf(R[7], p[2], notg[1])));
        float t2 = fmaf(R[2], p[0], fmaf(R[5], p[1], fmaf(R[8], p[2], notg[2])));
        float pos_err   = fmaf(t0, t0, fmaf(t1, t1, t2 * t2));
        float goal_dist = asqrt(pos_err);

        // d = I - G^T R ; rn[i] = ||d[i,:]||
        float rn[3];
        #pragma unroll
        for (int i = 0; i < 3; i++) {
            float rsq = 0.0f;
            #pragma unroll
            for (int j = 0; j < 3; j++) {
                float m = fmaf(G[i], R[j], fmaf(G[3 + i], R[3 + j], G[6 + i] * R[6 + j]));
                float d = (i == j ? 1.0f : 0.0f) - m;
                rsq = fmaf(d, d, rsq);
            }
            rn[i] = asqrt(rsq);
        }

        float rn_sum       = rn[0] + rn[1] + rn[2];
        float rot_err_norm = asqrt(fmaf(rn[0], rn[0], fmaf(rn[1], rn[1], rn[2] * rn[2])));
        // sqrt(rot_err) with hinge; rn_sum >= 0 so sqrt(rn_sum^2) = rn_sum
        float sq_rot = (goal_dist <= HINGE) ? rn_sum : 0.0f;

        out0[n] = sq_rot + goal_dist;   // WEIGHT = (1,1)
        out1[n] = rot_err_norm;
        out2[n] = goal_dist;

        __syncthreads();
        buf ^= 1;
        roff += rstep;
        poff += pstep;
        n    += nstep;
    }
}

extern "C" void kernel_launch(void* const* d_in, const int* in_sizes, int n_in,
                              void* d_out, int out_size) {
    // Bind inputs BY SIZE (robust to harness ordering):
    //   H*3 -> gpos, H*9 -> grot, B*H*3 -> pos, B*H*9 -> rot
    int idx[4] = {0, 1, 2, 3};
    for (int i = 1; i < 4; i++) {
        int v = idx[i];
        int j = i - 1;
        while (j >= 0 && in_sizes[idx[j]] > in_sizes[v]) { idx[j + 1] = idx[j]; j--; }
        idx[j + 1] = v;
    }
    const float* gpos = (const float*)d_in[idx[0]];
    const float* grot = (const float*)d_in[idx[1]];
    const float* pos  = (const float*)d_in[idx[2]];
    const float* rot  = (const float*)d_in[idx[3]];

    const int H = in_sizes[idx[0]] / 3;          // 256
    const int B = in_sizes[idx[3]] / (9 * H);    // 8192

    float* out = (float*)d_out;
    traj_cost_kernel<<<NCTA, 256>>>(pos, rot, gpos, grot, out, B);
}

// round 8
// speedup vs baseline: 1.2436x; 1.0153x over previous
#include <cuda_runtime.h>
#include <cstdint>

#define HVAL 256
#define HINGE 100.0f
#define NCTA 888          // 148 SMs * 6 CTAs: one resident wave
#define NSTAGE 3

// Approximate sqrt: x * rsqrt(x). rel err ~1e-7, tolerance is 1e-3.
__device__ __forceinline__ float asqrt(float x) {
    return x > 0.0f ? x * rsqrtf(x) : 0.0f;
}

__device__ __forceinline__ void cp_async16(uint32_t smem_dst, const void* gmem_src) {
    asm volatile("cp.async.cg.shared.global [%0], [%1], 16;\n"
                 :: "r"(smem_dst), "l"(gmem_src));
}
__device__ __forceinline__ void cp_commit() {
    asm volatile("cp.async.commit_group;\n");
}
template<int N>
__device__ __forceinline__ void cp_wait() {
    asm volatile("cp.async.wait_group %0;\n" :: "n"(N));
}

__global__ __launch_bounds__(256, 6)
void traj_cost_kernel(const float* __restrict__ pos,   // [B,H,3]
                      const float* __restrict__ rot,   // [B,H,3,3]
                      const float* __restrict__ gpos,  // [H,3]
                      const float* __restrict__ grot,  // [H,3,3]
                      float* __restrict__ out,         // [3,B*H]
                      int B)
{
    // 3-stage ring: (2304 + 768) floats * 4 B = 12.3 KB per stage, 36.9 KB total
    __shared__ float s_rot[NSTAGE][HVAL * 9];
    __shared__ float s_pos[NSTAGE][HVAL * 3];

    const int tid = threadIdx.x;
    const int h   = tid;

    // ---- Goal data: load ONCE into registers; precompute negated otg ----
    float G[9], notg[3];
    #pragma unroll
    for (int i = 0; i < 9; i++) G[i] = __ldg(&grot[h * 9 + i]);
    {
        float pg0 = __ldg(&gpos[h * 3 + 0]);
        float pg1 = __ldg(&gpos[h * 3 + 1]);
        float pg2 = __ldg(&gpos[h * 3 + 2]);
        #pragma unroll
        for (int i = 0; i < 3; i++)
            notg[i] = -fmaf(G[i], pg0, fmaf(G[3 + i], pg1, G[6 + i] * pg2));
    }

    uint32_t srot[NSTAGE], spos[NSTAGE];
    #pragma unroll
    for (int s = 0; s < NSTAGE; s++) {
        srot[s] = (uint32_t)__cvta_generic_to_shared(s_rot[s]);
        spos[s] = (uint32_t)__cvta_generic_to_shared(s_pos[s]);
    }

    // 32-bit incremental offsets (max index B*H*9 = 18.9M < 2^31)
    int roff = blockIdx.x * (HVAL * 9);
    int poff = blockIdx.x * (HVAL * 3);
    int n    = blockIdx.x * HVAL + h;
    const int rstep = NCTA * (HVAL * 9);
    const int pstep = NCTA * (HVAL * 3);
    const int nstep = NCTA * HVAL;
    const int BH    = B * HVAL;

    float* __restrict__ out0 = out;
    float* __restrict__ out1 = out + BH;
    float* __restrict__ out2 = out + 2 * BH;

    auto stage = [&](int s, int ro, int po) {
        const float4* rsrc = reinterpret_cast<const float4*>(rot + ro);
        cp_async16(srot[s] + (uint32_t)(tid      ) * 16, rsrc + tid);
        cp_async16(srot[s] + (uint32_t)(tid + 256) * 16, rsrc + tid + 256);
        if (tid < 64)
            cp_async16(srot[s] + (uint32_t)(tid + 512) * 16, rsrc + tid + 512);
        if (tid < 192) {
            const float4* psrc = reinterpret_cast<const float4*>(pos + po);
            cp_async16(spos[s] + (uint32_t)tid * 16, psrc + tid);
        }
        cp_commit();
    };

    int b   = blockIdx.x;
    int buf = 0;

    // Prologue: stage tiles for iterations 0 and 1 (prefetch distance 2)
    stage(0, roff, poff);
    if (b + NCTA < B)
        stage(1, roff + rstep, poff + pstep);

    for (; b < B; b += NCTA) {
        // Wait for current tile: all but final iteration can leave 1 group pending
        if (b + NCTA < B) cp_wait<1>(); else cp_wait<0>();
        __syncthreads();   // single barrier per tile (ring depth 3 makes the
                           // trailing barrier unnecessary: the buffer staged now
                           // was last read before this barrier)

        // Prefetch tile for iteration i+2 into the ring slot being retired
        if (b + 2 * NCTA < B)
            stage((buf + 2) % NSTAGE, roff + 2 * rstep, poff + 2 * pstep);

        float R[9], p[3];
        #pragma unroll
        for (int i = 0; i < 9; i++) R[i] = s_rot[buf][h * 9 + i];
        #pragma unroll
        for (int i = 0; i < 3; i++) p[i] = s_pos[buf][h * 3 + i];

        // t[i] = (R^T p)[i] - otg[i]
        float t0 = fmaf(R[0], p[0], fmaf(R[3], p[1], fmaf(R[6], p[2], notg[0])));
        float t1 = fmaf(R[1], p[0], fmaf(R[4], p[1], fmaf(R[7], p[2], notg[1])));
        float t2 = fmaf(R[2], p[0], fmaf(R[5], p[1], fmaf(R[8], p[2], notg[2])));
        float pos_err   = fmaf(t0, t0, fmaf(t1, t1, t2 * t2));
        float goal_dist = asqrt(pos_err);

        // d = I - G^T R ; rn[i] = ||d[i,:]||
        float rn[3];
        #pragma unroll
        for (int i = 0; i < 3; i++) {
            float rsq = 0.0f;
            #pragma unroll
            for (int j = 0; j < 3; j++) {
                float m = fmaf(G[i], R[j], fmaf(G[3 + i], R[3 + j], G[6 + i] * R[6 + j]));
                float d = (i == j ? 1.0f : 0.0f) - m;
                rsq = fmaf(d, d, rsq);
            }
            rn[i] = asqrt(rsq);
        }

        float rn_sum       = rn[0] + rn[1] + rn[2];
        float rot_err_norm = asqrt(fmaf(rn[0], rn[0], fmaf(rn[1], rn[1], rn[2] * rn[2])));
        float sq_rot = (goal_dist <= HINGE) ? rn_sum : 0.0f;  // sqrt(rn_sum^2)=rn_sum

        // Streaming stores: outputs are write-once, keep them out of L2's way
        __stcs(out0 + n, sq_rot + goal_dist);   // WEIGHT = (1,1)
        __stcs(out1 + n, rot_err_norm);
        __stcs(out2 + n, goal_dist);

        buf = (buf + 1) % NSTAGE;
        roff += rstep;
        poff += pstep;
        n    += nstep;
    }
}

extern "C" void kernel_launch(void* const* d_in, const int* in_sizes, int n_in,
                              void* d_out, int out_size) {
    // Bind inputs BY SIZE (robust to harness ordering):
    //   H*3 -> gpos, H*9 -> grot, B*H*3 -> pos, B*H*9 -> rot
    int idx[4] = {0, 1, 2, 3};
    for (int i = 1; i < 4; i++) {
        int v = idx[i];
        int j = i - 1;
        while (j >= 0 && in_sizes[idx[j]] > in_sizes[v]) { idx[j + 1] = idx[j]; j--; }
        idx[j + 1] = v;
    }
    const float* gpos = (const float*)d_in[idx[0]];
    const float* grot = (const float*)d_in[idx[1]];
    const float* pos  = (const float*)d_in[idx[2]];
    const float* rot  = (const float*)d_in[idx[3]];

    const int H = in_sizes[idx[0]] / 3;          // 256
    const int B = in_sizes[idx[3]] / (9 * H);    // 8192

    float* out = (float*)d_out;
    traj_cost_kernel<<<NCTA, 256>>>(pos, rot, gpos, grot, out, B);
}

// round 9
// speedup vs baseline: 1.2679x; 1.0195x over previous
#include <cuda_runtime.h>
#include <cstdint>

#define HVAL 256
#define HINGE 100.0f
#define NCTA 888          // 148 SMs * 6 CTAs: one resident wave
#define NSTAGE 3

// Single-instruction approximate sqrt (MUFU.SQRT). sqrt.approx(+0) = +0.
// All call sites pass FMA-accumulated sums of squares (never negative).
__device__ __forceinline__ float asqrt(float x) {
    float r;
    asm("sqrt.approx.f32 %0, %1;" : "=f"(r) : "f"(x));
    return r;
}

__device__ __forceinline__ void cp_async16(uint32_t smem_dst, const void* gmem_src) {
    asm volatile("cp.async.cg.shared.global [%0], [%1], 16;\n"
                 :: "r"(smem_dst), "l"(gmem_src));
}
__device__ __forceinline__ void cp_commit() {
    asm volatile("cp.async.commit_group;\n");
}
template<int N>
__device__ __forceinline__ void cp_wait() {
    asm volatile("cp.async.wait_group %0;\n" :: "n"(N));
}

__global__ __launch_bounds__(256, 6)
void traj_cost_kernel(const float* __restrict__ pos,   // [B,H,3]
                      const float* __restrict__ rot,   // [B,H,3,3]
                      const float* __restrict__ gpos,  // [H,3]
                      const float* __restrict__ grot,  // [H,3,3]
                      float* __restrict__ out,         // [3,B*H]
                      int B)
{
    // 3-stage ring: (2304 + 768) floats * 4 B = 12.3 KB per stage
    __shared__ float s_rot[NSTAGE][HVAL * 9];
    __shared__ float s_pos[NSTAGE][HVAL * 3];

    const int tid = threadIdx.x;
    const int h   = tid;

    // ---- Goal data: load ONCE into registers; precompute negated otg ----
    float G[9], notg[3];
    #pragma unroll
    for (int i = 0; i < 9; i++) G[i] = __ldg(&grot[h * 9 + i]);
    {
        float pg0 = __ldg(&gpos[h * 3 + 0]);
        float pg1 = __ldg(&gpos[h * 3 + 1]);
        float pg2 = __ldg(&gpos[h * 3 + 2]);
        #pragma unroll
        for (int i = 0; i < 3; i++)
            notg[i] = -fmaf(G[i], pg0, fmaf(G[3 + i], pg1, G[6 + i] * pg2));
    }

    uint32_t srot[NSTAGE], spos[NSTAGE];
    #pragma unroll
    for (int s = 0; s < NSTAGE; s++) {
        srot[s] = (uint32_t)__cvta_generic_to_shared(s_rot[s]);
        spos[s] = (uint32_t)__cvta_generic_to_shared(s_pos[s]);
    }

    // 32-bit incremental offsets (max index B*H*9 = 18.9M < 2^31)
    int roff = blockIdx.x * (HVAL * 9);
    int poff = blockIdx.x * (HVAL * 3);
    int n    = blockIdx.x * HVAL + h;
    const int rstep = NCTA * (HVAL * 9);
    const int pstep = NCTA * (HVAL * 3);
    const int nstep = NCTA * HVAL;
    const int BH    = B * HVAL;

    float* __restrict__ out0 = out;
    float* __restrict__ out1 = out + BH;
    float* __restrict__ out2 = out + 2 * BH;

    auto stage = [&](int s, int ro, int po) {
        const float4* rsrc = reinterpret_cast<const float4*>(rot + ro);
        cp_async16(srot[s] + (uint32_t)(tid      ) * 16, rsrc + tid);
        cp_async16(srot[s] + (uint32_t)(tid + 256) * 16, rsrc + tid + 256);
        if (tid < 64)
            cp_async16(srot[s] + (uint32_t)(tid + 512) * 16, rsrc + tid + 512);
        if (tid < 192) {
            const float4* psrc = reinterpret_cast<const float4*>(pos + po);
            cp_async16(spos[s] + (uint32_t)tid * 16, psrc + tid);
        }
        cp_commit();
    };

    int b   = blockIdx.x;
    int buf = 0;

    // Prologue: prefetch distance 2
    stage(0, roff, poff);
    if (b + NCTA < B)
        stage(1, roff + rstep, poff + pstep);

    for (; b < B; b += NCTA) {
        if (b + NCTA < B) cp_wait<1>(); else cp_wait<0>();
        __syncthreads();   // single barrier per tile (ring depth 3)

        if (b + 2 * NCTA < B)
            stage((buf + 2) % NSTAGE, roff + 2 * rstep, poff + 2 * pstep);

        float R[9], p[3];
        #pragma unroll
        for (int i = 0; i < 9; i++) R[i] = s_rot[buf][h * 9 + i];
        #pragma unroll
        for (int i = 0; i < 3; i++) p[i] = s_pos[buf][h * 3 + i];

        // t[i] = (R^T p)[i] - otg[i]
        float t0 = fmaf(R[0], p[0], fmaf(R[3], p[1], fmaf(R[6], p[2], notg[0])));
        float t1 = fmaf(R[1], p[0], fmaf(R[4], p[1], fmaf(R[7], p[2], notg[1])));
        float t2 = fmaf(R[2], p[0], fmaf(R[5], p[1], fmaf(R[8], p[2], notg[2])));
        float pos_err   = fmaf(t0, t0, fmaf(t1, t1, t2 * t2));
        float goal_dist = asqrt(pos_err);

        // d = I - G^T R : fold the -delta into the innermost FMA seed,
        // so d_ij = -(m'_ij) with m'_ij = G^T R - delta. d^2 unaffected by sign.
        float rn[3];
        #pragma unroll
        for (int i = 0; i < 3; i++) {
            float rsq = 0.0f;
            #pragma unroll
            for (int j = 0; j < 3; j++) {
                float seed = (i == j) ? -1.0f : 0.0f;
                float m = fmaf(G[i], R[j],
                          fmaf(G[3 + i], R[3 + j],
                          fmaf(G[6 + i], R[6 + j], seed)));
                rsq = fmaf(m, m, rsq);
            }
            rn[i] = asqrt(rsq);
        }

        float rn_sum       = rn[0] + rn[1] + rn[2];
        float rot_err_norm = asqrt(fmaf(rn[0], rn[0], fmaf(rn[1], rn[1], rn[2] * rn[2])));
        float sq_rot = (goal_dist <= HINGE) ? rn_sum : 0.0f;  // sqrt(rn_sum^2) = rn_sum

        __stcs(out0 + n, sq_rot + goal_dist);   // WEIGHT = (1,1)
        __stcs(out1 + n, rot_err_norm);
        __stcs(out2 + n, goal_dist);

        buf = (buf + 1) % NSTAGE;
        roff += rstep;
        poff += pstep;
        n    += nstep;
    }
}

extern "C" void kernel_launch(void* const* d_in, const int* in_sizes, int n_in,
                              void* d_out, int out_size) {
    // Bind inputs BY SIZE (robust to harness ordering):
    //   H*3 -> gpos, H*9 -> grot, B*H*3 -> pos, B*H*9 -> rot
    int idx[4] = {0, 1, 2, 3};
    for (int i = 1; i < 4; i++) {
        int v = idx[i];
        int j = i - 1;
        while (j >= 0 && in_sizes[idx[j]] > in_sizes[v]) { idx[j + 1] = idx[j]; j--; }
        idx[j + 1] = v;
    }
    const float* gpos = (const float*)d_in[idx[0]];
    const float* grot = (const float*)d_in[idx[1]];
    const float* pos  = (const float*)d_in[idx[2]];
    const float* rot  = (const float*)d_in[idx[3]];

    const int H = in_sizes[idx[0]] / 3;          // 256
    const int B = in_sizes[idx[3]] / (9 * H);    // 8192

    float* out = (float*)d_out;
    traj_cost_kernel<<<NCTA, 256>>>(pos, rot, gpos, grot, out, B);
}